// round 10
// baseline (speedup 1.0000x reference)
#include <cuda_runtime.h>
#include <cstdint>

#define N_CELLS_MAX 50048
#define N_EDGES_MAX 1600512
#define C 64
#define SCAN_B 512

// Scratch (allocation-free rule: __device__ globals)
__device__ float g_msg[N_CELLS_MAX * C];
__device__ float g_as[N_CELLS_MAX];
__device__ float g_ad[N_CELLS_MAX];
__device__ float g_rowsum[N_CELLS_MAX];
__device__ float g_e[N_EDGES_MAX];
__device__ int   g_deg[N_CELLS_MAX];
__device__ int   g_rowstart[N_CELLS_MAX + 1];
__device__ int   g_cursor[N_CELLS_MAX];
__device__ int   g_blockpart[128];
__device__ int2  g_csr[N_EDGES_MAX];   // (dst, bitcast coef)

// ---------------------------------------------------------------------------
// K1: msg = x @ W ; alpha via the EXACT frozen fmaf+shfl sequence per row.
// 8 rows per warp. UNCHANGED (passing since R7).
// ---------------------------------------------------------------------------
__global__ void __launch_bounds__(256) k_gemm_alpha(
    const float* __restrict__ x, const float* __restrict__ W,
    const float* __restrict__ a, int n)
{
    __shared__ float Ws[C * C];
    __shared__ float As[2 * C];
    int tid = threadIdx.x;
    for (int i = tid; i < C * C; i += blockDim.x) Ws[i] = W[i];
    if (tid < 2 * C) As[tid] = a[tid];
    __syncthreads();

    int warp = tid >> 5, lane = tid & 31;
    int row0 = (blockIdx.x * 8 + warp) * 8;
    if (row0 >= n) return;

    float xr0[8], xr1[8];
    #pragma unroll
    for (int r = 0; r < 8; r++) {
        int row = row0 + r;
        if (row < n) {
            const float* xr = x + (size_t)row * C;
            xr0[r] = xr[lane];
            xr1[r] = xr[lane + 32];
        } else {
            xr0[r] = 0.f;
            xr1[r] = 0.f;
        }
    }

    float acc0[8], acc1[8];
    #pragma unroll
    for (int r = 0; r < 8; r++) { acc0[r] = 0.f; acc1[r] = 0.f; }

    #pragma unroll
    for (int k = 0; k < 32; k++) {
        float w0 = Ws[k * C + lane];
        float w1 = Ws[k * C + lane + 32];
        #pragma unroll
        for (int r = 0; r < 8; r++) {
            float xv = __shfl_sync(0xffffffffu, xr0[r], k);
            acc0[r] = fmaf(xv, w0, acc0[r]);
            acc1[r] = fmaf(xv, w1, acc1[r]);
        }
    }
    #pragma unroll
    for (int k = 0; k < 32; k++) {
        float w0 = Ws[(k + 32) * C + lane];
        float w1 = Ws[(k + 32) * C + lane + 32];
        #pragma unroll
        for (int r = 0; r < 8; r++) {
            float xv = __shfl_sync(0xffffffffu, xr1[r], k);
            acc0[r] = fmaf(xv, w0, acc0[r]);
            acc1[r] = fmaf(xv, w1, acc1[r]);
        }
    }

    #pragma unroll
    for (int r = 0; r < 8; r++) {
        int row = row0 + r;
        bool ok = (row < n);
        if (ok) {
            g_msg[(size_t)row * C + lane]      = acc0[r];
            g_msg[(size_t)row * C + lane + 32] = acc1[r];
        }
        float s0 = acc0[r] * As[lane]     + acc1[r] * As[lane + 32];
        float s1 = acc0[r] * As[C + lane] + acc1[r] * As[C + lane + 32];
        #pragma unroll
        for (int o = 16; o > 0; o >>= 1) {
            s0 += __shfl_xor_sync(0xffffffffu, s0, o);
            s1 += __shfl_xor_sync(0xffffffffu, s1, o);
        }
        if (lane == 0 && ok) {
            g_as[row] = s0;
            g_ad[row] = s1;
            g_rowsum[row] = 0.f;
            g_deg[row] = 0;
        }
    }
}

// ---------------------------------------------------------------------------
// K2: e = LeakyReLU(as[src] + ad[dst]); rowsum[src]+=e; deg[src]++.
// Vectorized: 4 edges/thread via int4/float4. Per-edge float expressions
// IDENTICAL to the frozen scalar form (only atomic issue order shifts —
// in-band per measured R7/R9 variation).
// ---------------------------------------------------------------------------
__global__ void __launch_bounds__(256) k_edge_e(
    const int* __restrict__ src, const int* __restrict__ dst, int E)
{
    int i = (blockIdx.x * blockDim.x + threadIdx.x) * 4;
    if (i >= E) return;
    if (i + 3 < E) {
        int4 s = *(const int4*)(src + i);
        int4 d = *(const int4*)(dst + i);
        float v0 = g_as[s.x] + g_ad[d.x];
        float v1 = g_as[s.y] + g_ad[d.y];
        float v2 = g_as[s.z] + g_ad[d.z];
        float v3 = g_as[s.w] + g_ad[d.w];
        float e0 = v0 > 0.f ? v0 : 0.2f * v0;
        float e1 = v1 > 0.f ? v1 : 0.2f * v1;
        float e2 = v2 > 0.f ? v2 : 0.2f * v2;
        float e3 = v3 > 0.f ? v3 : 0.2f * v3;
        *(float4*)(g_e + i) = make_float4(e0, e1, e2, e3);
        atomicAdd(&g_rowsum[s.x], e0);
        atomicAdd(&g_rowsum[s.y], e1);
        atomicAdd(&g_rowsum[s.z], e2);
        atomicAdd(&g_rowsum[s.w], e3);
        atomicAdd(&g_deg[s.x], 1);
        atomicAdd(&g_deg[s.y], 1);
        atomicAdd(&g_deg[s.z], 1);
        atomicAdd(&g_deg[s.w], 1);
    } else {
        for (int e = i; e < E; e++) {
            int s = src[e], d = dst[e];
            float v = g_as[s] + g_ad[d];
            float ev_ = v > 0.f ? v : 0.2f * v;
            g_e[e] = ev_;
            atomicAdd(&g_rowsum[s], ev_);
            atomicAdd(&g_deg[s], 1);
        }
    }
}

// ---------------------------------------------------------------------------
// Scan stage 1: per-block sums of g_deg
// ---------------------------------------------------------------------------
__global__ void __launch_bounds__(SCAN_B) k_scan1(int n)
{
    __shared__ int wsum[16];
    int t = threadIdx.x;
    int gid = blockIdx.x * SCAN_B + t;
    int v = (gid < n) ? g_deg[gid] : 0;
    #pragma unroll
    for (int o = 16; o > 0; o >>= 1) v += __shfl_xor_sync(0xffffffffu, v, o);
    if ((t & 31) == 0) wsum[t >> 5] = v;
    __syncthreads();
    if (t < 32) {
        int s = (t < 16) ? wsum[t] : 0;
        #pragma unroll
        for (int o = 8; o > 0; o >>= 1) s += __shfl_xor_sync(0xffffffffu, s, o);
        if (t == 0) g_blockpart[blockIdx.x] = s;
    }
}

// ---------------------------------------------------------------------------
// Scan stage 2+3 fused, warp-shuffle based: scan block partials (<=128) with
// one warp, then 512-wide exclusive scan of g_deg via shfl (3 barriers).
// ---------------------------------------------------------------------------
__global__ void __launch_bounds__(SCAN_B) k_scan3(int n, int nb)
{
    __shared__ int part[4];     // 4 warps' inclusive sums over the partial array
    __shared__ int wincl[16];   // per-warp inclusive totals for the main scan
    int t = threadIdx.x;
    int lane = t & 31, wid = t >> 5;

    // --- scan of block partials: 128 values by 4 warps (warp-shfl) ---
    int base = 0;
    {
        int pv = (t < 128 && t < nb) ? g_blockpart[t] : 0;
        if (t < 128) {
            int x = pv;
            #pragma unroll
            for (int o = 1; o < 32; o <<= 1) {
                int y = __shfl_up_sync(0xffffffffu, x, o);
                if (lane >= o) x += y;
            }
            if (lane == 31) part[wid] = x;
        }
        __syncthreads();
        // prefix over the 4 warp sums (scalar, all threads)
        int p0 = part[0], p1 = part[1], p2 = part[2];
        int wbase[4] = {0, p0, p0 + p1, p0 + p1 + p2};
        if (t < 128) {
            int x = pv;
            #pragma unroll
            for (int o = 1; o < 32; o <<= 1) {
                int y = __shfl_up_sync(0xffffffffu, x, o);
                if (lane >= o) x += y;
            }
            // inclusive prefix of partials at index t = x + wbase[wid]
            // base for main block b is prefix over partials < b (exclusive)
        }
        // compute exclusive prefix for this block's index directly:
        // sum of g_blockpart[0..blockIdx.x-1]
        // Recompute via the warp data: do it with a shared array instead.
        __syncthreads();
        // Simple approach: warp 0 computes running prefix into shared array.
        __shared__ int pref[129];
        if (t == 0) {
            int run = 0;
            for (int b = 0; b < nb; b++) { pref[b] = run; run += g_blockpart[b]; }
        }
        __syncthreads();
        base = pref[blockIdx.x];
    }

    // --- main 512-wide exclusive scan via warp shuffles ---
    int gid = blockIdx.x * SCAN_B + t;
    int v = (gid < n) ? g_deg[gid] : 0;
    int x = v;
    #pragma unroll
    for (int o = 1; o < 32; o <<= 1) {
        int y = __shfl_up_sync(0xffffffffu, x, o);
        if (lane >= o) x += y;
    }
    if (lane == 31) wincl[wid] = x;
    __syncthreads();
    if (t < 32) {
        int s = (t < 16) ? wincl[t] : 0;
        #pragma unroll
        for (int o = 1; o < 16; o <<= 1) {
            int y = __shfl_up_sync(0xffffffffu, s, o);
            if ((t & 31) >= o) s += y;
        }
        if (t < 16) wincl[t] = s;   // inclusive warp prefix
    }
    __syncthreads();
    int wbase2 = (wid == 0) ? 0 : wincl[wid - 1];
    int excl = x - v + wbase2 + base;
    if (gid < n) {
        g_rowstart[gid] = excl;
        g_cursor[gid]   = excl;
        if (gid == n - 1) g_rowstart[n] = excl + v;
    }
}

// ---------------------------------------------------------------------------
// Build CSR with precomputed coef (frozen expression). 4 edges/thread.
// ---------------------------------------------------------------------------
__global__ void __launch_bounds__(256) k_build(
    const int* __restrict__ src, const int* __restrict__ dst,
    const float* __restrict__ ev, int E)
{
    int i = (blockIdx.x * blockDim.x + threadIdx.x) * 4;
    if (i >= E) return;
    if (i + 3 < E) {
        int4 s = *(const int4*)(src + i);
        int4 d = *(const int4*)(dst + i);
        float4 v = *(const float4*)(ev + i);
        float4 e = *(const float4*)(g_e + i);
        float c0 = e.x / g_rowsum[s.x] * v.x;
        float c1 = e.y / g_rowsum[s.y] * v.y;
        float c2 = e.z / g_rowsum[s.z] * v.z;
        float c3 = e.w / g_rowsum[s.w] * v.w;
        int p0 = atomicAdd(&g_cursor[s.x], 1);
        int p1 = atomicAdd(&g_cursor[s.y], 1);
        int p2 = atomicAdd(&g_cursor[s.z], 1);
        int p3 = atomicAdd(&g_cursor[s.w], 1);
        g_csr[p0] = make_int2(d.x, __float_as_int(c0));
        g_csr[p1] = make_int2(d.y, __float_as_int(c1));
        g_csr[p2] = make_int2(d.z, __float_as_int(c2));
        g_csr[p3] = make_int2(d.w, __float_as_int(c3));
    } else {
        for (int e = i; e < E; e++) {
            int s = src[e];
            float coef = g_e[e] / g_rowsum[s] * ev[e];
            int p = atomicAdd(&g_cursor[s], 1);
            g_csr[p] = make_int2(dst[e], __float_as_int(coef));
        }
    }
}

// ---------------------------------------------------------------------------
// K3: one warp per row, fp32 fma accumulation, 8-way MLP unroll. UNCHANGED.
// ---------------------------------------------------------------------------
__global__ void __launch_bounds__(256) k_row_aggregate(float* __restrict__ out, int n)
{
    int wid = threadIdx.x >> 5, lane = threadIdx.x & 31;
    int row = blockIdx.x * 8 + wid;
    if (row >= n) return;

    int beg = g_rowstart[row];
    int end = g_rowstart[row + 1];

    float a0 = 0.f, a1 = 0.f;
    int i = beg;
    for (; i + 8 <= end; i += 8) {
        int2 p[8];
        #pragma unroll
        for (int u = 0; u < 8; u++) p[u] = g_csr[i + u];
        float2 m[8];
        #pragma unroll
        for (int u = 0; u < 8; u++)
            m[u] = *(const float2*)&g_msg[(size_t)p[u].x * C + lane * 2];
        #pragma unroll
        for (int u = 0; u < 8; u++) {
            float c = __int_as_float(p[u].y);
            a0 = fmaf(c, m[u].x, a0);
            a1 = fmaf(c, m[u].y, a1);
        }
    }
    for (; i < end; i++) {
        int2 p = g_csr[i];
        float2 m = *(const float2*)&g_msg[(size_t)p.x * C + lane * 2];
        float c = __int_as_float(p.y);
        a0 = fmaf(c, m.x, a0);
        a1 = fmaf(c, m.y, a1);
    }
    *(float2*)&out[(size_t)row * C + lane * 2] = make_float2(a0, a1);
}

extern "C" void kernel_launch(void* const* d_in, const int* in_sizes, int n_in,
                              void* d_out, int out_size)
{
    const float* x_source   = (const float*)d_in[0];   // [n, 64]
    const int*   edge_index = (const int*)d_in[1];     // [2, E]
    const float* edge_vals  = (const float*)d_in[2];   // [E]
    const float* W          = (const float*)d_in[3];   // [64, 64]
    const float* a          = (const float*)d_in[4];   // [128]
    float* out = (float*)d_out;

    int n = in_sizes[0] / C;
    int E = in_sizes[2];
    const int* src = edge_index;
    const int* dst = edge_index + E;

    // K1: 8 rows/warp, 8 warps -> 64 rows per block
    int blocks1 = (n + 63) / 64;
    k_gemm_alpha<<<blocks1, 256>>>(x_source, W, a, n);

    // K2: 4 edges/thread
    int blocks2 = (E + 4 * 256 - 1) / (4 * 256);
    k_edge_e<<<blocks2, 256>>>(src, dst, E);

    // CSR build
    int nb = (n + SCAN_B - 1) / SCAN_B;
    k_scan1<<<nb, SCAN_B>>>(n);
    k_scan3<<<nb, SCAN_B>>>(n, nb);
    k_build<<<blocks2, 256>>>(src, dst, edge_vals, E);

    // K3: one warp per row
    int blocks3 = (n + 7) / 8;
    k_row_aggregate<<<blocks3, 256>>>(out, n);
}

// round 12
// speedup vs baseline: 1.1497x; 1.1497x over previous
#include <cuda_runtime.h>
#include <cstdint>

#define N_CELLS_MAX 50048
#define N_EDGES_MAX 1600512
#define C 64
#define SCAN_B 512
#define DEG_CAP 128

// Scratch (allocation-free rule: __device__ globals)
__device__ float g_msg[N_CELLS_MAX * C];
__device__ float g_as[N_CELLS_MAX];
__device__ float g_ad[N_CELLS_MAX];
__device__ int   g_deg[N_CELLS_MAX];
__device__ int   g_rowstart[N_CELLS_MAX + 1];
__device__ int   g_cursor[N_CELLS_MAX];
__device__ int   g_blockpart[128];
__device__ int2  g_csr[N_EDGES_MAX];   // (dst, bitcast edge_value) — no float deps!

// ---------------------------------------------------------------------------
// K1: msg = x @ W ; alpha via the EXACT frozen fmaf+shfl sequence per row.
// 8 rows per warp. UNCHANGED (passing since R7). Zeroes g_deg.
// ---------------------------------------------------------------------------
__global__ void __launch_bounds__(256) k_gemm_alpha(
    const float* __restrict__ x, const float* __restrict__ W,
    const float* __restrict__ a, int n)
{
    __shared__ float Ws[C * C];
    __shared__ float As[2 * C];
    int tid = threadIdx.x;
    for (int i = tid; i < C * C; i += blockDim.x) Ws[i] = W[i];
    if (tid < 2 * C) As[tid] = a[tid];
    __syncthreads();

    int warp = tid >> 5, lane = tid & 31;
    int row0 = (blockIdx.x * 8 + warp) * 8;
    if (row0 >= n) return;

    float xr0[8], xr1[8];
    #pragma unroll
    for (int r = 0; r < 8; r++) {
        int row = row0 + r;
        if (row < n) {
            const float* xr = x + (size_t)row * C;
            xr0[r] = xr[lane];
            xr1[r] = xr[lane + 32];
        } else {
            xr0[r] = 0.f;
            xr1[r] = 0.f;
        }
    }

    float acc0[8], acc1[8];
    #pragma unroll
    for (int r = 0; r < 8; r++) { acc0[r] = 0.f; acc1[r] = 0.f; }

    #pragma unroll
    for (int k = 0; k < 32; k++) {
        float w0 = Ws[k * C + lane];
        float w1 = Ws[k * C + lane + 32];
        #pragma unroll
        for (int r = 0; r < 8; r++) {
            float xv = __shfl_sync(0xffffffffu, xr0[r], k);
            acc0[r] = fmaf(xv, w0, acc0[r]);
            acc1[r] = fmaf(xv, w1, acc1[r]);
        }
    }
    #pragma unroll
    for (int k = 0; k < 32; k++) {
        float w0 = Ws[(k + 32) * C + lane];
        float w1 = Ws[(k + 32) * C + lane + 32];
        #pragma unroll
        for (int r = 0; r < 8; r++) {
            float xv = __shfl_sync(0xffffffffu, xr1[r], k);
            acc0[r] = fmaf(xv, w0, acc0[r]);
            acc1[r] = fmaf(xv, w1, acc1[r]);
        }
    }

    #pragma unroll
    for (int r = 0; r < 8; r++) {
        int row = row0 + r;
        bool ok = (row < n);
        if (ok) {
            g_msg[(size_t)row * C + lane]      = acc0[r];
            g_msg[(size_t)row * C + lane + 32] = acc1[r];
        }
        float s0 = acc0[r] * As[lane]     + acc1[r] * As[lane + 32];
        float s1 = acc0[r] * As[C + lane] + acc1[r] * As[C + lane + 32];
        #pragma unroll
        for (int o = 16; o > 0; o >>= 1) {
            s0 += __shfl_xor_sync(0xffffffffu, s0, o);
            s1 += __shfl_xor_sync(0xffffffffu, s1, o);
        }
        if (lane == 0 && ok) {
            g_as[row] = s0;
            g_ad[row] = s1;
            g_deg[row] = 0;
        }
    }
}

// ---------------------------------------------------------------------------
// k_deg: degree histogram from src only (int atomics, order-free).
// ---------------------------------------------------------------------------
__global__ void __launch_bounds__(256) k_deg(const int* __restrict__ src, int E)
{
    int i = (blockIdx.x * blockDim.x + threadIdx.x) * 4;
    if (i >= E) return;
    if (i + 3 < E) {
        int4 s = *(const int4*)(src + i);
        atomicAdd(&g_deg[s.x], 1);
        atomicAdd(&g_deg[s.y], 1);
        atomicAdd(&g_deg[s.z], 1);
        atomicAdd(&g_deg[s.w], 1);
    } else {
        for (int e = i; e < E; e++) atomicAdd(&g_deg[src[e]], 1);
    }
}

// ---------------------------------------------------------------------------
// Scan stage 1: per-block sums of g_deg (warp shuffles)
// ---------------------------------------------------------------------------
__global__ void __launch_bounds__(SCAN_B) k_scan1(int n)
{
    __shared__ int wsum[16];
    int t = threadIdx.x;
    int gid = blockIdx.x * SCAN_B + t;
    int v = (gid < n) ? g_deg[gid] : 0;
    #pragma unroll
    for (int o = 16; o > 0; o >>= 1) v += __shfl_xor_sync(0xffffffffu, v, o);
    if ((t & 31) == 0) wsum[t >> 5] = v;
    __syncthreads();
    if (t < 32) {
        int s = (t < 16) ? wsum[t] : 0;
        #pragma unroll
        for (int o = 8; o > 0; o >>= 1) s += __shfl_xor_sync(0xffffffffu, s, o);
        if (t == 0) g_blockpart[blockIdx.x] = s;
    }
}

// ---------------------------------------------------------------------------
// Scan stage 2+3 fused. Parallel prefix of <=128 block partials (no serial
// loop), then 512-wide exclusive scan of g_deg via warp shuffles.
// ---------------------------------------------------------------------------
__global__ void __launch_bounds__(SCAN_B) k_scan3(int n, int nb)
{
    __shared__ int part[4];
    __shared__ int pref[128];   // inclusive prefix of partials
    __shared__ int wincl[16];
    int t = threadIdx.x;
    int lane = t & 31, wid = t >> 5;

    // parallel inclusive scan of partials (threads 0..127, 4 warps)
    int x128 = 0;
    if (t < 128) {
        int pv = (t < nb) ? g_blockpart[t] : 0;
        x128 = pv;
        #pragma unroll
        for (int o = 1; o < 32; o <<= 1) {
            int y = __shfl_up_sync(0xffffffffu, x128, o);
            if (lane >= o) x128 += y;
        }
        if (lane == 31) part[wid] = x128;
    }
    __syncthreads();
    if (t < 128) {
        int wb = 0;
        #pragma unroll
        for (int w = 0; w < 4; w++) if (w < wid) wb += part[w];
        pref[t] = x128 + wb;
    }
    __syncthreads();
    int base = (blockIdx.x == 0) ? 0 : pref[blockIdx.x - 1];

    // main 512-wide exclusive scan
    int gid = blockIdx.x * SCAN_B + t;
    int v = (gid < n) ? g_deg[gid] : 0;
    int x = v;
    #pragma unroll
    for (int o = 1; o < 32; o <<= 1) {
        int y = __shfl_up_sync(0xffffffffu, x, o);
        if (lane >= o) x += y;
    }
    if (lane == 31) wincl[wid] = x;
    __syncthreads();
    if (t < 32) {
        int s = (t < 16) ? wincl[t] : 0;
        #pragma unroll
        for (int o = 1; o < 16; o <<= 1) {
            int y = __shfl_up_sync(0xffffffffu, s, o);
            if (t >= o) s += y;
        }
        if (t < 16) wincl[t] = s;
    }
    __syncthreads();
    int wbase = (wid == 0) ? 0 : wincl[wid - 1];
    int excl = x - v + wbase + base;
    if (gid < n) {
        g_rowstart[gid] = excl;
        g_cursor[gid]   = excl;
        if (gid == n - 1) g_rowstart[n] = excl + v;
    }
}

// ---------------------------------------------------------------------------
// k_build: scatter (dst, edge_value) into CSR. No float dependencies.
// ---------------------------------------------------------------------------
__global__ void __launch_bounds__(256) k_build(
    const int* __restrict__ src, const int* __restrict__ dst,
    const float* __restrict__ ev, int E)
{
    int i = (blockIdx.x * blockDim.x + threadIdx.x) * 4;
    if (i >= E) return;
    if (i + 3 < E) {
        int4 s = *(const int4*)(src + i);
        int4 d = *(const int4*)(dst + i);
        float4 v = *(const float4*)(ev + i);
        int p0 = atomicAdd(&g_cursor[s.x], 1);
        int p1 = atomicAdd(&g_cursor[s.y], 1);
        int p2 = atomicAdd(&g_cursor[s.z], 1);
        int p3 = atomicAdd(&g_cursor[s.w], 1);
        g_csr[p0] = make_int2(d.x, __float_as_int(v.x));
        g_csr[p1] = make_int2(d.y, __float_as_int(v.y));
        g_csr[p2] = make_int2(d.z, __float_as_int(v.z));
        g_csr[p3] = make_int2(d.w, __float_as_int(v.w));
    } else {
        for (int e = i; e < E; e++) {
            int p = atomicAdd(&g_cursor[src[e]], 1);
            g_csr[p] = make_int2(dst[e], __float_as_int(ev[e]));
        }
    }
}

// ---------------------------------------------------------------------------
// K3': one warp per row, everything fused:
//   pass1 (lane-strided): e = lrelu(as[row] + ad[dst]); smem-cache e; warp-
//          deterministic rowsum (lane partials + butterfly).
//   pass1b (lane-strided): coef = (e / rsf) * ev  — frozen expression; divs
//          parallelized across lanes.
//   pass2 (warp per edge): out += coef * msg[dst], fp32 fma, 8-way MLP.
// ---------------------------------------------------------------------------
__global__ void __launch_bounds__(256) k_row_aggregate(float* __restrict__ out, int n)
{
    __shared__ float c_s[8][DEG_CAP];
    int wid = threadIdx.x >> 5, lane = threadIdx.x & 31;
    int row = blockIdx.x * 8 + wid;
    if (row >= n) return;

    int beg = g_rowstart[row];
    int end = g_rowstart[row + 1];
    int deg = end - beg;
    float as_r = g_as[row];

    // pass1: e values + deterministic rowsum
    float rs = 0.f;
    for (int i = lane; i < deg; i += 32) {
        int2 p = g_csr[beg + i];
        float v = as_r + g_ad[p.x];
        float e = v > 0.f ? v : 0.2f * v;
        if (i < DEG_CAP) c_s[wid][i] = e;
        rs += e;
    }
    #pragma unroll
    for (int o = 16; o > 0; o >>= 1)
        rs += __shfl_xor_sync(0xffffffffu, rs, o);
    float rsf = rs;

    // pass1b: coef into smem (each lane reads only its own writes)
    int dcap = deg < DEG_CAP ? deg : DEG_CAP;
    for (int i = lane; i < dcap; i += 32) {
        int2 p = g_csr[beg + i];
        c_s[wid][i] = (c_s[wid][i] / rsf) * __int_as_float(p.y);
    }
    __syncwarp();

    // pass2: gather + accumulate
    float a0 = 0.f, a1 = 0.f;
    int i = beg;
    int endc = beg + dcap;
    for (; i + 8 <= endc; i += 8) {
        int2 p[8];
        #pragma unroll
        for (int u = 0; u < 8; u++) p[u] = g_csr[i + u];
        float2 m[8];
        #pragma unroll
        for (int u = 0; u < 8; u++)
            m[u] = *(const float2*)&g_msg[(size_t)p[u].x * C + lane * 2];
        #pragma unroll
        for (int u = 0; u < 8; u++) {
            float c = c_s[wid][i + u - beg];
            a0 = fmaf(c, m[u].x, a0);
            a1 = fmaf(c, m[u].y, a1);
        }
    }
    for (; i < endc; i++) {
        int2 p = g_csr[i];
        float2 m = *(const float2*)&g_msg[(size_t)p.x * C + lane * 2];
        float c = c_s[wid][i - beg];
        a0 = fmaf(c, m.x, a0);
        a1 = fmaf(c, m.y, a1);
    }
    for (; i < end; i++) {            // deg > DEG_CAP overflow (≈ never)
        int2 p = g_csr[i];
        float v = as_r + g_ad[p.x];
        float e = v > 0.f ? v : 0.2f * v;
        float c = (e / rsf) * __int_as_float(p.y);
        float2 m = *(const float2*)&g_msg[(size_t)p.x * C + lane * 2];
        a0 = fmaf(c, m.x, a0);
        a1 = fmaf(c, m.y, a1);
    }
    *(float2*)&out[(size_t)row * C + lane * 2] = make_float2(a0, a1);
}

extern "C" void kernel_launch(void* const* d_in, const int* in_sizes, int n_in,
                              void* d_out, int out_size)
{
    const float* x_source   = (const float*)d_in[0];   // [n, 64]
    const int*   edge_index = (const int*)d_in[1];     // [2, E]
    const float* edge_vals  = (const float*)d_in[2];   // [E]
    const float* W          = (const float*)d_in[3];   // [64, 64]
    const float* a          = (const float*)d_in[4];   // [128]
    float* out = (float*)d_out;

    int n = in_sizes[0] / C;
    int E = in_sizes[2];
    const int* src = edge_index;
    const int* dst = edge_index + E;

    // K1 first (zeroes g_deg), then the integer CSR pipeline, then K3'.
    int blocks1 = (n + 63) / 64;
    k_gemm_alpha<<<blocks1, 256>>>(x_source, W, a, n);

    int blocksE = (E + 4 * 256 - 1) / (4 * 256);
    k_deg<<<blocksE, 256>>>(src, E);

    int nb = (n + SCAN_B - 1) / SCAN_B;
    k_scan1<<<nb, SCAN_B>>>(n);
    k_scan3<<<nb, SCAN_B>>>(n, nb);
    k_build<<<blocksE, 256>>>(src, dst, edge_vals, E);

    int blocks3 = (n + 7) / 8;
    k_row_aggregate<<<blocks3, 256>>>(out, n);
}

// round 14
// speedup vs baseline: 1.1926x; 1.0372x over previous
#include <cuda_runtime.h>
#include <cstdint>

#define N_CELLS_MAX 50048
#define N_EDGES_MAX 1600512
#define C 64
#define SCAN_B 512
#define DEG_CAP 128

// Scratch (allocation-free rule: __device__ globals)
__device__ float g_msg[N_CELLS_MAX * C];
__device__ float g_as[N_CELLS_MAX];
__device__ float g_ad[N_CELLS_MAX];
__device__ int   g_deg[N_CELLS_MAX];
__device__ int   g_rowstart[N_CELLS_MAX + 1];
__device__ int   g_cursor[N_CELLS_MAX];
__device__ int   g_blockpart[128];
__device__ int2  g_csr[N_EDGES_MAX];   // (dst, bitcast edge_value) — no float deps

// Stream/event for the independent integer CSR chain. Created once at static
// init (host objects; no device-memory alloc; no per-call state).
static cudaStream_t g_s2;
static cudaEvent_t g_ev_fork, g_ev_join;
static struct _StreamInit {
    _StreamInit() {
        cudaStreamCreateWithFlags(&g_s2, cudaStreamNonBlocking);
        cudaEventCreateWithFlags(&g_ev_fork, cudaEventDisableTiming);
        cudaEventCreateWithFlags(&g_ev_join, cudaEventDisableTiming);
    }
} _streamInit;

// ---------------------------------------------------------------------------
// K1: msg = x @ W ; alpha via the EXACT frozen fmaf+shfl sequence per row.
// 8 rows per warp. UNCHANGED float ops (passing since R7).
// NOTE: g_deg zeroing moved to k_zero (stream 2) — K1 now runs concurrently
// with the integer chain and must not touch its data.
// ---------------------------------------------------------------------------
__global__ void __launch_bounds__(256) k_gemm_alpha(
    const float* __restrict__ x, const float* __restrict__ W,
    const float* __restrict__ a, int n)
{
    __shared__ float Ws[C * C];
    __shared__ float As[2 * C];
    int tid = threadIdx.x;
    for (int i = tid; i < C * C; i += blockDim.x) Ws[i] = W[i];
    if (tid < 2 * C) As[tid] = a[tid];
    __syncthreads();

    int warp = tid >> 5, lane = tid & 31;
    int row0 = (blockIdx.x * 8 + warp) * 8;
    if (row0 >= n) return;

    float xr0[8], xr1[8];
    #pragma unroll
    for (int r = 0; r < 8; r++) {
        int row = row0 + r;
        if (row < n) {
            const float* xr = x + (size_t)row * C;
            xr0[r] = xr[lane];
            xr1[r] = xr[lane + 32];
        } else {
            xr0[r] = 0.f;
            xr1[r] = 0.f;
        }
    }

    float acc0[8], acc1[8];
    #pragma unroll
    for (int r = 0; r < 8; r++) { acc0[r] = 0.f; acc1[r] = 0.f; }

    #pragma unroll
    for (int k = 0; k < 32; k++) {
        float w0 = Ws[k * C + lane];
        float w1 = Ws[k * C + lane + 32];
        #pragma unroll
        for (int r = 0; r < 8; r++) {
            float xv = __shfl_sync(0xffffffffu, xr0[r], k);
            acc0[r] = fmaf(xv, w0, acc0[r]);
            acc1[r] = fmaf(xv, w1, acc1[r]);
        }
    }
    #pragma unroll
    for (int k = 0; k < 32; k++) {
        float w0 = Ws[(k + 32) * C + lane];
        float w1 = Ws[(k + 32) * C + lane + 32];
        #pragma unroll
        for (int r = 0; r < 8; r++) {
            float xv = __shfl_sync(0xffffffffu, xr1[r], k);
            acc0[r] = fmaf(xv, w0, acc0[r]);
            acc1[r] = fmaf(xv, w1, acc1[r]);
        }
    }

    #pragma unroll
    for (int r = 0; r < 8; r++) {
        int row = row0 + r;
        bool ok = (row < n);
        if (ok) {
            g_msg[(size_t)row * C + lane]      = acc0[r];
            g_msg[(size_t)row * C + lane + 32] = acc1[r];
        }
        float s0 = acc0[r] * As[lane]     + acc1[r] * As[lane + 32];
        float s1 = acc0[r] * As[C + lane] + acc1[r] * As[C + lane + 32];
        #pragma unroll
        for (int o = 16; o > 0; o >>= 1) {
            s0 += __shfl_xor_sync(0xffffffffu, s0, o);
            s1 += __shfl_xor_sync(0xffffffffu, s1, o);
        }
        if (lane == 0 && ok) {
            g_as[row] = s0;
            g_ad[row] = s1;
        }
    }
}

// ---------------------------------------------------------------------------
// k_zero: zero the degree histogram (stream 2 head).
// ---------------------------------------------------------------------------
__global__ void __launch_bounds__(256) k_zero(int n)
{
    int i = blockIdx.x * blockDim.x + threadIdx.x;
    if (i < n) g_deg[i] = 0;
}

// ---------------------------------------------------------------------------
// k_deg: degree histogram from src only (int atomics, order-free).
// ---------------------------------------------------------------------------
__global__ void __launch_bounds__(256) k_deg(const int* __restrict__ src, int E)
{
    int i = (blockIdx.x * blockDim.x + threadIdx.x) * 4;
    if (i >= E) return;
    if (i + 3 < E) {
        int4 s = *(const int4*)(src + i);
        atomicAdd(&g_deg[s.x], 1);
        atomicAdd(&g_deg[s.y], 1);
        atomicAdd(&g_deg[s.z], 1);
        atomicAdd(&g_deg[s.w], 1);
    } else {
        for (int e = i; e < E; e++) atomicAdd(&g_deg[src[e]], 1);
    }
}

// ---------------------------------------------------------------------------
// Scan stage 1: per-block sums of g_deg (warp shuffles)
// ---------------------------------------------------------------------------
__global__ void __launch_bounds__(SCAN_B) k_scan1(int n)
{
    __shared__ int wsum[16];
    int t = threadIdx.x;
    int gid = blockIdx.x * SCAN_B + t;
    int v = (gid < n) ? g_deg[gid] : 0;
    #pragma unroll
    for (int o = 16; o > 0; o >>= 1) v += __shfl_xor_sync(0xffffffffu, v, o);
    if ((t & 31) == 0) wsum[t >> 5] = v;
    __syncthreads();
    if (t < 32) {
        int s = (t < 16) ? wsum[t] : 0;
        #pragma unroll
        for (int o = 8; o > 0; o >>= 1) s += __shfl_xor_sync(0xffffffffu, s, o);
        if (t == 0) g_blockpart[blockIdx.x] = s;
    }
}

// ---------------------------------------------------------------------------
// Scan stage 2+3 fused: parallel prefix of <=128 block partials, then
// 512-wide exclusive scan of g_deg via warp shuffles.
// ---------------------------------------------------------------------------
__global__ void __launch_bounds__(SCAN_B) k_scan3(int n, int nb)
{
    __shared__ int part[4];
    __shared__ int pref[128];
    __shared__ int wincl[16];
    int t = threadIdx.x;
    int lane = t & 31, wid = t >> 5;

    int x128 = 0;
    if (t < 128) {
        int pv = (t < nb) ? g_blockpart[t] : 0;
        x128 = pv;
        #pragma unroll
        for (int o = 1; o < 32; o <<= 1) {
            int y = __shfl_up_sync(0xffffffffu, x128, o);
            if (lane >= o) x128 += y;
        }
        if (lane == 31) part[wid] = x128;
    }
    __syncthreads();
    if (t < 128) {
        int wb = 0;
        #pragma unroll
        for (int w = 0; w < 4; w++) if (w < wid) wb += part[w];
        pref[t] = x128 + wb;
    }
    __syncthreads();
    int base = (blockIdx.x == 0) ? 0 : pref[blockIdx.x - 1];

    int gid = blockIdx.x * SCAN_B + t;
    int v = (gid < n) ? g_deg[gid] : 0;
    int x = v;
    #pragma unroll
    for (int o = 1; o < 32; o <<= 1) {
        int y = __shfl_up_sync(0xffffffffu, x, o);
        if (lane >= o) x += y;
    }
    if (lane == 31) wincl[wid] = x;
    __syncthreads();
    if (t < 32) {
        int s = (t < 16) ? wincl[t] : 0;
        #pragma unroll
        for (int o = 1; o < 16; o <<= 1) {
            int y = __shfl_up_sync(0xffffffffu, s, o);
            if (t >= o) s += y;
        }
        if (t < 16) wincl[t] = s;
    }
    __syncthreads();
    int wbase = (wid == 0) ? 0 : wincl[wid - 1];
    int excl = x - v + wbase + base;
    if (gid < n) {
        g_rowstart[gid] = excl;
        g_cursor[gid]   = excl;
        if (gid == n - 1) g_rowstart[n] = excl + v;
    }
}

// ---------------------------------------------------------------------------
// k_build: scatter (dst, edge_value) into CSR. No float dependencies.
// ---------------------------------------------------------------------------
__global__ void __launch_bounds__(256) k_build(
    const int* __restrict__ src, const int* __restrict__ dst,
    const float* __restrict__ ev, int E)
{
    int i = (blockIdx.x * blockDim.x + threadIdx.x) * 4;
    if (i >= E) return;
    if (i + 3 < E) {
        int4 s = *(const int4*)(src + i);
        int4 d = *(const int4*)(dst + i);
        float4 v = *(const float4*)(ev + i);
        int p0 = atomicAdd(&g_cursor[s.x], 1);
        int p1 = atomicAdd(&g_cursor[s.y], 1);
        int p2 = atomicAdd(&g_cursor[s.z], 1);
        int p3 = atomicAdd(&g_cursor[s.w], 1);
        g_csr[p0] = make_int2(d.x, __float_as_int(v.x));
        g_csr[p1] = make_int2(d.y, __float_as_int(v.y));
        g_csr[p2] = make_int2(d.z, __float_as_int(v.z));
        g_csr[p3] = make_int2(d.w, __float_as_int(v.w));
    } else {
        for (int e = i; e < E; e++) {
            int p = atomicAdd(&g_cursor[src[e]], 1);
            g_csr[p] = make_int2(dst[e], __float_as_int(ev[e]));
        }
    }
}

// ---------------------------------------------------------------------------
// K3': one warp per row, fused (frozen expressions, same as R12):
//   pass1: csr read ONCE; cache dst/ev/e in smem; deterministic butterfly
//          rowsum.
//   pass1b: coef = (e / rsf) * ev (lane-owned smem, no sync needed).
//   pass2: out += coef * msg[dst] from smem-cached dst (no csr re-read).
// ---------------------------------------------------------------------------
__global__ void __launch_bounds__(256) k_row_aggregate(float* __restrict__ out, int n)
{
    __shared__ float c_s[8][DEG_CAP];
    __shared__ float ev_s[8][DEG_CAP];
    __shared__ int   d_s[8][DEG_CAP];
    int wid = threadIdx.x >> 5, lane = threadIdx.x & 31;
    int row = blockIdx.x * 8 + wid;
    if (row >= n) return;

    int beg = g_rowstart[row];
    int end = g_rowstart[row + 1];
    int deg = end - beg;
    float as_r = g_as[row];

    // pass1: e values + deterministic rowsum; cache dst/ev
    float rs = 0.f;
    for (int i = lane; i < deg; i += 32) {
        int2 p = g_csr[beg + i];
        float v = as_r + g_ad[p.x];
        float e = v > 0.f ? v : 0.2f * v;
        if (i < DEG_CAP) {
            c_s[wid][i]  = e;
            ev_s[wid][i] = __int_as_float(p.y);
            d_s[wid][i]  = p.x;
        }
        rs += e;
    }
    #pragma unroll
    for (int o = 16; o > 0; o >>= 1)
        rs += __shfl_xor_sync(0xffffffffu, rs, o);
    float rsf = rs;

    // pass1b: coef in-place (each lane reads only its own writes)
    int dcap = deg < DEG_CAP ? deg : DEG_CAP;
    for (int i = lane; i < dcap; i += 32)
        c_s[wid][i] = (c_s[wid][i] / rsf) * ev_s[wid][i];
    __syncwarp();

    // pass2: gather + accumulate (dst from smem)
    float a0 = 0.f, a1 = 0.f;
    int i = 0;
    for (; i + 8 <= dcap; i += 8) {
        int dd[8];
        #pragma unroll
        for (int u = 0; u < 8; u++) dd[u] = d_s[wid][i + u];
        float2 m[8];
        #pragma unroll
        for (int u = 0; u < 8; u++)
            m[u] = *(const float2*)&g_msg[(size_t)dd[u] * C + lane * 2];
        #pragma unroll
        for (int u = 0; u < 8; u++) {
            float c = c_s[wid][i + u];
            a0 = fmaf(c, m[u].x, a0);
            a1 = fmaf(c, m[u].y, a1);
        }
    }
    for (; i < dcap; i++) {
        float2 m = *(const float2*)&g_msg[(size_t)d_s[wid][i] * C + lane * 2];
        float c = c_s[wid][i];
        a0 = fmaf(c, m.x, a0);
        a1 = fmaf(c, m.y, a1);
    }
    for (int j = beg + dcap; j < end; j++) {   // deg > DEG_CAP overflow (≈ never)
        int2 p = g_csr[j];
        float v = as_r + g_ad[p.x];
        float e = v > 0.f ? v : 0.2f * v;
        float c = (e / rsf) * __int_as_float(p.y);
        float2 m = *(const float2*)&g_msg[(size_t)p.x * C + lane * 2];
        a0 = fmaf(c, m.x, a0);
        a1 = fmaf(c, m.y, a1);
    }
    *(float2*)&out[(size_t)row * C + lane * 2] = make_float2(a0, a1);
}

extern "C" void kernel_launch(void* const* d_in, const int* in_sizes, int n_in,
                              void* d_out, int out_size)
{
    const float* x_source   = (const float*)d_in[0];   // [n, 64]
    const int*   edge_index = (const int*)d_in[1];     // [2, E]
    const float* edge_vals  = (const float*)d_in[2];   // [E]
    const float* W          = (const float*)d_in[3];   // [64, 64]
    const float* a          = (const float*)d_in[4];   // [128]
    float* out = (float*)d_out;

    int n = in_sizes[0] / C;
    int E = in_sizes[2];
    const int* src = edge_index;
    const int* dst = edge_index + E;

    // Fork: integer CSR chain on g_s2, K1 on the main stream — independent.
    cudaEventRecord(g_ev_fork, 0);
    cudaStreamWaitEvent(g_s2, g_ev_fork, 0);

    // Main stream: K1 (FMA-bound, ~24us)
    int blocks1 = (n + 63) / 64;
    k_gemm_alpha<<<blocks1, 256>>>(x_source, W, a, n);

    // Stream 2: zero -> deg -> scan -> build (~21us, no K1 dependency)
    int blocksZ = (n + 255) / 256;
    k_zero<<<blocksZ, 256, 0, g_s2>>>(n);
    int blocksE = (E + 4 * 256 - 1) / (4 * 256);
    k_deg<<<blocksE, 256, 0, g_s2>>>(src, E);
    int nb = (n + SCAN_B - 1) / SCAN_B;
    k_scan1<<<nb, SCAN_B, 0, g_s2>>>(n);
    k_scan3<<<nb, SCAN_B, 0, g_s2>>>(n, nb);
    k_build<<<blocksE, 256, 0, g_s2>>>(src, dst, edge_vals, E);

    // Join: K3' needs both K1's outputs and the CSR.
    cudaEventRecord(g_ev_join, g_s2);
    cudaStreamWaitEvent(0, g_ev_join, 0);

    int blocks3 = (n + 7) / 8;
    k_row_aggregate<<<blocks3, 256>>>(out, n);
}

// round 16
// speedup vs baseline: 1.2458x; 1.0446x over previous
#include <cuda_runtime.h>
#include <cstdint>

#define N_CELLS_MAX 50048
#define N_EDGES_MAX 1600512
#define C 64
#define SCAN_B 512
#define DEG_CAP 128

// Scratch (allocation-free rule: __device__ globals)
__device__ float g_msg[N_CELLS_MAX * C];
__device__ float g_as[N_CELLS_MAX];
__device__ float g_ad[N_CELLS_MAX];
__device__ int   g_deg[N_CELLS_MAX];       // zero at start of every run:
                                           // BSS-zero initially; K3' re-zeroes.
__device__ int   g_rowstart[N_CELLS_MAX + 1];
__device__ int   g_cursor[N_CELLS_MAX];
__device__ int   g_blockpart[128];
__device__ int2  g_csr[N_EDGES_MAX];       // (dst, bitcast edge_value)

static cudaStream_t g_s2;
static cudaEvent_t g_ev_fork, g_ev_join;
static struct _StreamInit {
    _StreamInit() {
        cudaStreamCreateWithFlags(&g_s2, cudaStreamNonBlocking);
        cudaEventCreateWithFlags(&g_ev_fork, cudaEventDisableTiming);
        cudaEventCreateWithFlags(&g_ev_join, cudaEventDisableTiming);
    }
} _streamInit;

// ---------------------------------------------------------------------------
// K1: msg = x @ W ; alpha via the frozen fmaf sequence (k = 0..63 per
// accumulator, unchanged). PERF CHANGE ONLY: x values come from an smem tile
// via broadcast LDS (float4 over k) instead of warp shuffles. Same values,
// same fmaf order -> bit-identical acc/alpha.
// ---------------------------------------------------------------------------
__global__ void __launch_bounds__(256) k_gemm_alpha(
    const float* __restrict__ x, const float* __restrict__ W,
    const float* __restrict__ a, int n)
{
    __shared__ float Ws[C * C];
    __shared__ float As[2 * C];
    __shared__ float xs[64][64];     // 64 rows of x for this block
    int tid = threadIdx.x;
    for (int i = tid; i < C * C; i += blockDim.x) Ws[i] = W[i];
    if (tid < 2 * C) As[tid] = a[tid];

    int row0blk = blockIdx.x * 64;
    {
        const float4* xv = (const float4*)x;
        #pragma unroll
        for (int i = 0; i < 4; i++) {
            int idx = tid + i * 256;          // 0..1023
            int r  = idx >> 4;
            int c4 = idx & 15;
            int grow = row0blk + r;
            float4 v = make_float4(0.f, 0.f, 0.f, 0.f);
            if (grow < n) v = xv[(size_t)grow * 16 + c4];
            *(float4*)&xs[r][c4 * 4] = v;
        }
    }
    __syncthreads();

    int warp = tid >> 5, lane = tid & 31;
    int wrow0 = warp * 8;                      // this warp's 8 rows in the tile
    int row0 = row0blk + wrow0;
    if (row0 >= n) return;

    float acc0[8], acc1[8];
    #pragma unroll
    for (int r = 0; r < 8; r++) { acc0[r] = 0.f; acc1[r] = 0.f; }

    #pragma unroll
    for (int k4 = 0; k4 < 16; k4++) {
        // W operands for these 4 ks (conflict-free stride-1 LDS)
        float w0[4], w1[4];
        #pragma unroll
        for (int kk = 0; kk < 4; kk++) {
            w0[kk] = Ws[(k4 * 4 + kk) * C + lane];
            w1[kk] = Ws[(k4 * 4 + kk) * C + lane + 32];
        }
        #pragma unroll
        for (int r = 0; r < 8; r++) {
            float4 xv4 = *(const float4*)&xs[wrow0 + r][k4 * 4];  // broadcast
            acc0[r] = fmaf(xv4.x, w0[0], acc0[r]);
            acc1[r] = fmaf(xv4.x, w1[0], acc1[r]);
            acc0[r] = fmaf(xv4.y, w0[1], acc0[r]);
            acc1[r] = fmaf(xv4.y, w1[1], acc1[r]);
            acc0[r] = fmaf(xv4.z, w0[2], acc0[r]);
            acc1[r] = fmaf(xv4.z, w1[2], acc1[r]);
            acc0[r] = fmaf(xv4.w, w0[3], acc0[r]);
            acc1[r] = fmaf(xv4.w, w1[3], acc1[r]);
        }
    }

    #pragma unroll
    for (int r = 0; r < 8; r++) {
        int row = row0 + r;
        bool ok = (row < n);
        if (ok) {
            g_msg[(size_t)row * C + lane]      = acc0[r];
            g_msg[(size_t)row * C + lane + 32] = acc1[r];
        }
        // Frozen alpha expression + 32-lane butterfly (unchanged).
        float s0 = acc0[r] * As[lane]     + acc1[r] * As[lane + 32];
        float s1 = acc0[r] * As[C + lane] + acc1[r] * As[C + lane + 32];
        #pragma unroll
        for (int o = 16; o > 0; o >>= 1) {
            s0 += __shfl_xor_sync(0xffffffffu, s0, o);
            s1 += __shfl_xor_sync(0xffffffffu, s1, o);
        }
        if (lane == 0 && ok) {
            g_as[row] = s0;
            g_ad[row] = s1;
        }
    }
}

// ---------------------------------------------------------------------------
// k_deg: degree histogram from src (int atomics). g_deg arrives zeroed.
// ---------------------------------------------------------------------------
__global__ void __launch_bounds__(256) k_deg(const int* __restrict__ src, int E)
{
    int i = (blockIdx.x * blockDim.x + threadIdx.x) * 4;
    if (i >= E) return;
    if (i + 3 < E) {
        int4 s = *(const int4*)(src + i);
        atomicAdd(&g_deg[s.x], 1);
        atomicAdd(&g_deg[s.y], 1);
        atomicAdd(&g_deg[s.z], 1);
        atomicAdd(&g_deg[s.w], 1);
    } else {
        for (int e = i; e < E; e++) atomicAdd(&g_deg[src[e]], 1);
    }
}

// ---------------------------------------------------------------------------
// Scan stage 1: per-block sums of g_deg (warp shuffles)
// ---------------------------------------------------------------------------
__global__ void __launch_bounds__(SCAN_B) k_scan1(int n)
{
    __shared__ int wsum[16];
    int t = threadIdx.x;
    int gid = blockIdx.x * SCAN_B + t;
    int v = (gid < n) ? g_deg[gid] : 0;
    #pragma unroll
    for (int o = 16; o > 0; o >>= 1) v += __shfl_xor_sync(0xffffffffu, v, o);
    if ((t & 31) == 0) wsum[t >> 5] = v;
    __syncthreads();
    if (t < 32) {
        int s = (t < 16) ? wsum[t] : 0;
        #pragma unroll
        for (int o = 8; o > 0; o >>= 1) s += __shfl_xor_sync(0xffffffffu, s, o);
        if (t == 0) g_blockpart[blockIdx.x] = s;
    }
}

// ---------------------------------------------------------------------------
// Scan stage 2+3 fused (parallel partials prefix + 512-wide shfl scan)
// ---------------------------------------------------------------------------
__global__ void __launch_bounds__(SCAN_B) k_scan3(int n, int nb)
{
    __shared__ int part[4];
    __shared__ int pref[128];
    __shared__ int wincl[16];
    int t = threadIdx.x;
    int lane = t & 31, wid = t >> 5;

    int x128 = 0;
    if (t < 128) {
        int pv = (t < nb) ? g_blockpart[t] : 0;
        x128 = pv;
        #pragma unroll
        for (int o = 1; o < 32; o <<= 1) {
            int y = __shfl_up_sync(0xffffffffu, x128, o);
            if (lane >= o) x128 += y;
        }
        if (lane == 31) part[wid] = x128;
    }
    __syncthreads();
    if (t < 128) {
        int wb = 0;
        #pragma unroll
        for (int w = 0; w < 4; w++) if (w < wid) wb += part[w];
        pref[t] = x128 + wb;
    }
    __syncthreads();
    int base = (blockIdx.x == 0) ? 0 : pref[blockIdx.x - 1];

    int gid = blockIdx.x * SCAN_B + t;
    int v = (gid < n) ? g_deg[gid] : 0;
    int x = v;
    #pragma unroll
    for (int o = 1; o < 32; o <<= 1) {
        int y = __shfl_up_sync(0xffffffffu, x, o);
        if (lane >= o) x += y;
    }
    if (lane == 31) wincl[wid] = x;
    __syncthreads();
    if (t < 32) {
        int s = (t < 16) ? wincl[t] : 0;
        #pragma unroll
        for (int o = 1; o < 16; o <<= 1) {
            int y = __shfl_up_sync(0xffffffffu, s, o);
            if (t >= o) s += y;
        }
        if (t < 16) wincl[t] = s;
    }
    __syncthreads();
    int wbase = (wid == 0) ? 0 : wincl[wid - 1];
    int excl = x - v + wbase + base;
    if (gid < n) {
        g_rowstart[gid] = excl;
        g_cursor[gid]   = excl;
        if (gid == n - 1) g_rowstart[n] = excl + v;
    }
}

// ---------------------------------------------------------------------------
// k_build: scatter (dst, edge_value) into CSR. No float dependencies.
// ---------------------------------------------------------------------------
__global__ void __launch_bounds__(256) k_build(
    const int* __restrict__ src, const int* __restrict__ dst,
    const float* __restrict__ ev, int E)
{
    int i = (blockIdx.x * blockDim.x + threadIdx.x) * 4;
    if (i >= E) return;
    if (i + 3 < E) {
        int4 s = *(const int4*)(src + i);
        int4 d = *(const int4*)(dst + i);
        float4 v = *(const float4*)(ev + i);
        int p0 = atomicAdd(&g_cursor[s.x], 1);
        int p1 = atomicAdd(&g_cursor[s.y], 1);
        int p2 = atomicAdd(&g_cursor[s.z], 1);
        int p3 = atomicAdd(&g_cursor[s.w], 1);
        g_csr[p0] = make_int2(d.x, __float_as_int(v.x));
        g_csr[p1] = make_int2(d.y, __float_as_int(v.y));
        g_csr[p2] = make_int2(d.z, __float_as_int(v.z));
        g_csr[p3] = make_int2(d.w, __float_as_int(v.w));
    } else {
        for (int e = i; e < E; e++) {
            int p = atomicAdd(&g_cursor[src[e]], 1);
            g_csr[p] = make_int2(dst[e], __float_as_int(ev[e]));
        }
    }
}

// ---------------------------------------------------------------------------
// K3': one warp per row, fused (frozen expressions, same as R12/R14).
// Tail: re-zero g_deg[row] so the next replay starts from a clean histogram
// (self-maintaining invariant; initially true from BSS zero-init).
// ---------------------------------------------------------------------------
__global__ void __launch_bounds__(256) k_row_aggregate(float* __restrict__ out, int n)
{
    __shared__ float c_s[8][DEG_CAP];
    __shared__ float ev_s[8][DEG_CAP];
    __shared__ int   d_s[8][DEG_CAP];
    int wid = threadIdx.x >> 5, lane = threadIdx.x & 31;
    int row = blockIdx.x * 8 + wid;
    if (row >= n) return;

    int beg = g_rowstart[row];
    int end = g_rowstart[row + 1];
    int deg = end - beg;
    float as_r = g_as[row];

    float rs = 0.f;
    for (int i = lane; i < deg; i += 32) {
        int2 p = g_csr[beg + i];
        float v = as_r + g_ad[p.x];
        float e = v > 0.f ? v : 0.2f * v;
        if (i < DEG_CAP) {
            c_s[wid][i]  = e;
            ev_s[wid][i] = __int_as_float(p.y);
            d_s[wid][i]  = p.x;
        }
        rs += e;
    }
    #pragma unroll
    for (int o = 16; o > 0; o >>= 1)
        rs += __shfl_xor_sync(0xffffffffu, rs, o);
    float rsf = rs;

    int dcap = deg < DEG_CAP ? deg : DEG_CAP;
    for (int i = lane; i < dcap; i += 32)
        c_s[wid][i] = (c_s[wid][i] / rsf) * ev_s[wid][i];
    __syncwarp();

    float a0 = 0.f, a1 = 0.f;
    int i = 0;
    for (; i + 8 <= dcap; i += 8) {
        int dd[8];
        #pragma unroll
        for (int u = 0; u < 8; u++) dd[u] = d_s[wid][i + u];
        float2 m[8];
        #pragma unroll
        for (int u = 0; u < 8; u++)
            m[u] = *(const float2*)&g_msg[(size_t)dd[u] * C + lane * 2];
        #pragma unroll
        for (int u = 0; u < 8; u++) {
            float c = c_s[wid][i + u];
            a0 = fmaf(c, m[u].x, a0);
            a1 = fmaf(c, m[u].y, a1);
        }
    }
    for (; i < dcap; i++) {
        float2 m = *(const float2*)&g_msg[(size_t)d_s[wid][i] * C + lane * 2];
        float c = c_s[wid][i];
        a0 = fmaf(c, m.x, a0);
        a1 = fmaf(c, m.y, a1);
    }
    for (int j = beg + dcap; j < end; j++) {
        int2 p = g_csr[j];
        float v = as_r + g_ad[p.x];
        float e = v > 0.f ? v : 0.2f * v;
        float c = (e / rsf) * __int_as_float(p.y);
        float2 m = *(const float2*)&g_msg[(size_t)p.x * C + lane * 2];
        a0 = fmaf(c, m.x, a0);
        a1 = fmaf(c, m.y, a1);
    }
    *(float2*)&out[(size_t)row * C + lane * 2] = make_float2(a0, a1);

    if (lane == 0) g_deg[row] = 0;   // reset for next replay
}

extern "C" void kernel_launch(void* const* d_in, const int* in_sizes, int n_in,
                              void* d_out, int out_size)
{
    const float* x_source   = (const float*)d_in[0];   // [n, 64]
    const int*   edge_index = (const int*)d_in[1];     // [2, E]
    const float* edge_vals  = (const float*)d_in[2];   // [E]
    const float* W          = (const float*)d_in[3];   // [64, 64]
    const float* a          = (const float*)d_in[4];   // [128]
    float* out = (float*)d_out;

    int n = in_sizes[0] / C;
    int E = in_sizes[2];
    const int* src = edge_index;
    const int* dst = edge_index + E;

    // Fork: integer CSR chain on g_s2, K1 on the main stream.
    cudaEventRecord(g_ev_fork, 0);
    cudaStreamWaitEvent(g_s2, g_ev_fork, 0);

    int blocks1 = (n + 63) / 64;
    k_gemm_alpha<<<blocks1, 256>>>(x_source, W, a, n);

    int blocksE = (E + 4 * 256 - 1) / (4 * 256);
    k_deg<<<blocksE, 256, 0, g_s2>>>(src, E);
    int nb = (n + SCAN_B - 1) / SCAN_B;
    k_scan1<<<nb, SCAN_B, 0, g_s2>>>(n);
    k_scan3<<<nb, SCAN_B, 0, g_s2>>>(n, nb);
    k_build<<<blocksE, 256, 0, g_s2>>>(src, dst, edge_vals, E);

    cudaEventRecord(g_ev_join, g_s2);
    cudaStreamWaitEvent(0, g_ev_join, 0);

    int blocks3 = (n + 7) / 8;
    k_row_aggregate<<<blocks3, 256>>>(out, n);
}

// round 17
// speedup vs baseline: 1.3247x; 1.0634x over previous
#include <cuda_runtime.h>
#include <cstdint>

#define N_CELLS_MAX 50048
#define N_EDGES_MAX 1600512
#define C 64
#define SCAN_B 512
#define DEG_CAP 128

// Scratch (allocation-free rule: __device__ globals)
__device__ float g_msg[N_CELLS_MAX * C];
__device__ float g_as[N_CELLS_MAX];
__device__ float g_ad[N_CELLS_MAX];
__device__ int   g_deg[N_CELLS_MAX];       // BSS-zero; K3' tail re-zeroes.
__device__ int   g_rowstart[N_CELLS_MAX + 1];
__device__ int   g_cursor[N_CELLS_MAX];
__device__ int   g_ticket;                               // monotonic across replays
__device__ unsigned long long g_agg[128];                // epoch-tagged aggregates
__device__ int2  g_csr[N_EDGES_MAX];       // (dst, bitcast edge_value)

static cudaStream_t g_s2;
static cudaEvent_t g_ev_fork, g_ev_join;
static struct _StreamInit {
    _StreamInit() {
        cudaStreamCreateWithFlags(&g_s2, cudaStreamNonBlocking);
        cudaEventCreateWithFlags(&g_ev_fork, cudaEventDisableTiming);
        cudaEventCreateWithFlags(&g_ev_join, cudaEventDisableTiming);
    }
} _streamInit;

// ---------------------------------------------------------------------------
// K1: msg = x @ W ; frozen fmaf sequence (k = 0..63 ascending per acc);
// x via smem broadcast. UNCHANGED from R16 (passing).
// ---------------------------------------------------------------------------
__global__ void __launch_bounds__(256) k_gemm_alpha(
    const float* __restrict__ x, const float* __restrict__ W,
    const float* __restrict__ a, int n)
{
    __shared__ float Ws[C * C];
    __shared__ float As[2 * C];
    __shared__ float xs[64][64];
    int tid = threadIdx.x;
    for (int i = tid; i < C * C; i += blockDim.x) Ws[i] = W[i];
    if (tid < 2 * C) As[tid] = a[tid];

    int row0blk = blockIdx.x * 64;
    {
        const float4* xv = (const float4*)x;
        #pragma unroll
        for (int i = 0; i < 4; i++) {
            int idx = tid + i * 256;
            int r  = idx >> 4;
            int c4 = idx & 15;
            int grow = row0blk + r;
            float4 v = make_float4(0.f, 0.f, 0.f, 0.f);
            if (grow < n) v = xv[(size_t)grow * 16 + c4];
            *(float4*)&xs[r][c4 * 4] = v;
        }
    }
    __syncthreads();

    int warp = tid >> 5, lane = tid & 31;
    int wrow0 = warp * 8;
    int row0 = row0blk + wrow0;
    if (row0 >= n) return;

    float acc0[8], acc1[8];
    #pragma unroll
    for (int r = 0; r < 8; r++) { acc0[r] = 0.f; acc1[r] = 0.f; }

    #pragma unroll
    for (int k4 = 0; k4 < 16; k4++) {
        float w0[4], w1[4];
        #pragma unroll
        for (int kk = 0; kk < 4; kk++) {
            w0[kk] = Ws[(k4 * 4 + kk) * C + lane];
            w1[kk] = Ws[(k4 * 4 + kk) * C + lane + 32];
        }
        #pragma unroll
        for (int r = 0; r < 8; r++) {
            float4 xv4 = *(const float4*)&xs[wrow0 + r][k4 * 4];
            acc0[r] = fmaf(xv4.x, w0[0], acc0[r]);
            acc1[r] = fmaf(xv4.x, w1[0], acc1[r]);
            acc0[r] = fmaf(xv4.y, w0[1], acc0[r]);
            acc1[r] = fmaf(xv4.y, w1[1], acc1[r]);
            acc0[r] = fmaf(xv4.z, w0[2], acc0[r]);
            acc1[r] = fmaf(xv4.z, w1[2], acc1[r]);
            acc0[r] = fmaf(xv4.w, w0[3], acc0[r]);
            acc1[r] = fmaf(xv4.w, w1[3], acc1[r]);
        }
    }

    #pragma unroll
    for (int r = 0; r < 8; r++) {
        int row = row0 + r;
        bool ok = (row < n);
        if (ok) {
            g_msg[(size_t)row * C + lane]      = acc0[r];
            g_msg[(size_t)row * C + lane + 32] = acc1[r];
        }
        float s0 = acc0[r] * As[lane]     + acc1[r] * As[lane + 32];
        float s1 = acc0[r] * As[C + lane] + acc1[r] * As[C + lane + 32];
        #pragma unroll
        for (int o = 16; o > 0; o >>= 1) {
            s0 += __shfl_xor_sync(0xffffffffu, s0, o);
            s1 += __shfl_xor_sync(0xffffffffu, s1, o);
        }
        if (lane == 0 && ok) {
            g_as[row] = s0;
            g_ad[row] = s1;
        }
    }
}

// ---------------------------------------------------------------------------
// k_deg: degree histogram from src (int atomics). g_deg arrives zeroed.
// ---------------------------------------------------------------------------
__global__ void __launch_bounds__(256) k_deg(const int* __restrict__ src, int E)
{
    int i = (blockIdx.x * blockDim.x + threadIdx.x) * 4;
    if (i >= E) return;
    if (i + 3 < E) {
        int4 s = *(const int4*)(src + i);
        atomicAdd(&g_deg[s.x], 1);
        atomicAdd(&g_deg[s.y], 1);
        atomicAdd(&g_deg[s.z], 1);
        atomicAdd(&g_deg[s.w], 1);
    } else {
        for (int e = i; e < E; e++) atomicAdd(&g_deg[src[e]], 1);
    }
}

// ---------------------------------------------------------------------------
// k_scan: single-kernel exclusive scan with decoupled aggregate lookback.
// Epoch-tagged aggregates (tag = epoch+1 in high 32 bits) self-reset across
// graph replays; ticket assigns logical block ids. No circular wait: a block
// only spins on lower-ticket blocks, which never wait on higher tickets.
// ---------------------------------------------------------------------------
__global__ void __launch_bounds__(SCAN_B) k_scan(int n, int nb)
{
    __shared__ int smbid;
    __shared__ int wincl[16];
    __shared__ int rsum[16];
    int t = threadIdx.x;
    int lane = t & 31, wid = t >> 5;

    if (t == 0) smbid = atomicAdd(&g_ticket, 1);
    __syncthreads();
    int ticket = smbid;
    int epoch = ticket / nb;
    int bid   = ticket % nb;
    unsigned tag = (unsigned)(epoch + 1);

    // local inclusive scan of this block's 512 elements
    int gid = bid * SCAN_B + t;
    int v = (gid < n) ? g_deg[gid] : 0;
    int x = v;
    #pragma unroll
    for (int o = 1; o < 32; o <<= 1) {
        int y = __shfl_up_sync(0xffffffffu, x, o);
        if (lane >= o) x += y;
    }
    if (lane == 31) wincl[wid] = x;
    __syncthreads();
    if (t < 32) {
        int s = (t < 16) ? wincl[t] : 0;
        #pragma unroll
        for (int o = 1; o < 16; o <<= 1) {
            int y = __shfl_up_sync(0xffffffffu, s, o);
            if (t >= o) s += y;
        }
        if (t < 16) wincl[t] = s;
        // publish block aggregate ASAP (inclusive sum of all 16 warps)
        if (t == 0) {
            // wincl[15] not yet visible to t==0's registers; recompute:
        }
    }
    __syncthreads();
    int agg = wincl[15];
    if (t == 0)
        atomicExch(&g_agg[bid], ((unsigned long long)tag << 32) | (unsigned)agg);

    // lookback: threads t < bid spin-read predecessor aggregates (parallel)
    int my = 0;
    if (t < bid) {   // bid <= 127 < 512: one predecessor per thread
        unsigned long long pv;
        do { pv = atomicAdd(&g_agg[t], 0ULL); } while ((unsigned)(pv >> 32) != tag);
        my = (int)(unsigned)pv;
    }
    // block-reduce 'my' -> base
    #pragma unroll
    for (int o = 16; o > 0; o >>= 1) my += __shfl_xor_sync(0xffffffffu, my, o);
    if (lane == 0) rsum[wid] = my;
    __syncthreads();
    int base = 0;
    if (t < 32) {
        int s = (t < 16) ? rsum[t] : 0;
        #pragma unroll
        for (int o = 8; o > 0; o >>= 1) s += __shfl_xor_sync(0xffffffffu, s, o);
        if (t == 0) rsum[0] = s;
    }
    __syncthreads();
    base = rsum[0];

    int wbase = (wid == 0) ? 0 : wincl[wid - 1];
    int excl = x - v + wbase + base;
    if (gid < n) {
        g_rowstart[gid] = excl;
        g_cursor[gid]   = excl;
        if (gid == n - 1) g_rowstart[n] = excl + v;
    }
}

// ---------------------------------------------------------------------------
// k_build: scatter (dst, edge_value) into CSR. No float dependencies.
// ---------------------------------------------------------------------------
__global__ void __launch_bounds__(256) k_build(
    const int* __restrict__ src, const int* __restrict__ dst,
    const float* __restrict__ ev, int E)
{
    int i = (blockIdx.x * blockDim.x + threadIdx.x) * 4;
    if (i >= E) return;
    if (i + 3 < E) {
        int4 s = *(const int4*)(src + i);
        int4 d = *(const int4*)(dst + i);
        float4 v = *(const float4*)(ev + i);
        int p0 = atomicAdd(&g_cursor[s.x], 1);
        int p1 = atomicAdd(&g_cursor[s.y], 1);
        int p2 = atomicAdd(&g_cursor[s.z], 1);
        int p3 = atomicAdd(&g_cursor[s.w], 1);
        g_csr[p0] = make_int2(d.x, __float_as_int(v.x));
        g_csr[p1] = make_int2(d.y, __float_as_int(v.y));
        g_csr[p2] = make_int2(d.z, __float_as_int(v.z));
        g_csr[p3] = make_int2(d.w, __float_as_int(v.w));
    } else {
        for (int e = i; e < E; e++) {
            int p = atomicAdd(&g_cursor[src[e]], 1);
            g_csr[p] = make_int2(dst[e], __float_as_int(ev[e]));
        }
    }
}

// ---------------------------------------------------------------------------
// K3': one warp per row. pass1/pass1b frozen. pass2: 2 edges per warp-step,
// 16 lanes x float4 per edge; per-channel sum splits into two edge partials
// combined by shfl_xor(16) (output-sum reorder only — measured-safe per
// R7-vs-R8 fp32/fp64 equivalence). Tail: re-zero g_deg[row].
// ---------------------------------------------------------------------------
__global__ void __launch_bounds__(256) k_row_aggregate(float* __restrict__ out, int n)
{
    __shared__ float c_s[8][DEG_CAP];
    __shared__ float ev_s[8][DEG_CAP];
    __shared__ int   d_s[8][DEG_CAP];
    int wid = threadIdx.x >> 5, lane = threadIdx.x & 31;
    int row = blockIdx.x * 8 + wid;
    if (row >= n) return;

    int beg = g_rowstart[row];
    int end = g_rowstart[row + 1];
    int deg = end - beg;
    float as_r = g_as[row];

    // pass1: e + deterministic butterfly rowsum; cache dst/ev (frozen)
    float rs = 0.f;
    for (int i = lane; i < deg; i += 32) {
        int2 p = g_csr[beg + i];
        float v = as_r + g_ad[p.x];
        float e = v > 0.f ? v : 0.2f * v;
        if (i < DEG_CAP) {
            c_s[wid][i]  = e;
            ev_s[wid][i] = __int_as_float(p.y);
            d_s[wid][i]  = p.x;
        }
        rs += e;
    }
    #pragma unroll
    for (int o = 16; o > 0; o >>= 1)
        rs += __shfl_xor_sync(0xffffffffu, rs, o);
    float rsf = rs;

    // pass1b: coef (frozen expression)
    int dcap = deg < DEG_CAP ? deg : DEG_CAP;
    for (int i = lane; i < dcap; i += 32)
        c_s[wid][i] = (c_s[wid][i] / rsf) * ev_s[wid][i];
    __syncwarp();

    // pass2: sub = which edge of the pair, sl = float4 channel chunk
    int sub = lane >> 4;        // 0 or 1
    int sl  = lane & 15;        // channels sl*4 .. sl*4+3
    float a0 = 0.f, a1 = 0.f, a2 = 0.f, a3 = 0.f;
    int i = 0;
    for (; i + 8 <= dcap; i += 8) {
        #pragma unroll
        for (int u = 0; u < 4; u++) {
            int e_idx = i + u * 2 + sub;
            int d = d_s[wid][e_idx];
            float c = c_s[wid][e_idx];
            float4 m = *(const float4*)&g_msg[(size_t)d * C + sl * 4];
            a0 = fmaf(c, m.x, a0);
            a1 = fmaf(c, m.y, a1);
            a2 = fmaf(c, m.z, a2);
            a3 = fmaf(c, m.w, a3);
        }
    }
    for (; i + 2 <= dcap; i += 2) {
        int e_idx = i + sub;
        int d = d_s[wid][e_idx];
        float c = c_s[wid][e_idx];
        float4 m = *(const float4*)&g_msg[(size_t)d * C + sl * 4];
        a0 = fmaf(c, m.x, a0);
        a1 = fmaf(c, m.y, a1);
        a2 = fmaf(c, m.z, a2);
        a3 = fmaf(c, m.w, a3);
    }
    if (i < dcap) {             // odd remainder: sub==0 lanes do it
        int d = d_s[wid][i];
        float c = (sub == 0) ? c_s[wid][i] : 0.f;
        float4 m = *(const float4*)&g_msg[(size_t)d * C + sl * 4];
        a0 = fmaf(c, m.x, a0);
        a1 = fmaf(c, m.y, a1);
        a2 = fmaf(c, m.z, a2);
        a3 = fmaf(c, m.w, a3);
    }
    for (int j = beg + dcap; j < end; j++) {   // deg > DEG_CAP (≈ never)
        int2 p = g_csr[j];
        float v = as_r + g_ad[p.x];
        float e = v > 0.f ? v : 0.2f * v;
        float c = (sub == 0) ? (e / rsf) * __int_as_float(p.y) : 0.f;
        float4 m = *(const float4*)&g_msg[(size_t)p.x * C + sl * 4];
        a0 = fmaf(c, m.x, a0);
        a1 = fmaf(c, m.y, a1);
        a2 = fmaf(c, m.z, a2);
        a3 = fmaf(c, m.w, a3);
    }
    // combine the two edge partials (sub 0/1) per channel
    a0 += __shfl_xor_sync(0xffffffffu, a0, 16);
    a1 += __shfl_xor_sync(0xffffffffu, a1, 16);
    a2 += __shfl_xor_sync(0xffffffffu, a2, 16);
    a3 += __shfl_xor_sync(0xffffffffu, a3, 16);
    if (sub == 0)
        *(float4*)&out[(size_t)row * C + sl * 4] = make_float4(a0, a1, a2, a3);

    if (lane == 0) g_deg[row] = 0;   // reset for next replay
}

extern "C" void kernel_launch(void* const* d_in, const int* in_sizes, int n_in,
                              void* d_out, int out_size)
{
    const float* x_source   = (const float*)d_in[0];   // [n, 64]
    const int*   edge_index = (const int*)d_in[1];     // [2, E]
    const float* edge_vals  = (const float*)d_in[2];   // [E]
    const float* W          = (const float*)d_in[3];   // [64, 64]
    const float* a          = (const float*)d_in[4];   // [128]
    float* out = (float*)d_out;

    int n = in_sizes[0] / C;
    int E = in_sizes[2];
    const int* src = edge_index;
    const int* dst = edge_index + E;

    // Fork: integer CSR chain on g_s2, K1 on the main stream.
    cudaEventRecord(g_ev_fork, 0);
    cudaStreamWaitEvent(g_s2, g_ev_fork, 0);

    int blocks1 = (n + 63) / 64;
    k_gemm_alpha<<<blocks1, 256>>>(x_source, W, a, n);

    int blocksE = (E + 4 * 256 - 1) / (4 * 256);
    k_deg<<<blocksE, 256, 0, g_s2>>>(src, E);
    int nb = (n + SCAN_B - 1) / SCAN_B;
    k_scan<<<nb, SCAN_B, 0, g_s2>>>(n, nb);
    k_build<<<blocksE, 256, 0, g_s2>>>(src, dst, edge_vals, E);

    cudaEventRecord(g_ev_join, g_s2);
    cudaStreamWaitEvent(0, g_ev_join, 0);

    int blocks3 = (n + 7) / 8;
    k_row_aggregate<<<blocks3, 256>>>(out, n);
}